// round 13
// baseline (speedup 1.0000x reference)
#include <cuda_runtime.h>
#include <cuda_fp16.h>
#include <stdint.h>

#define Nn   8192
#define FIN  512
#define FOUT 128
#define HID  16
#define NF   (Nn*FOUT)

// ---------------- scratch (device globals: allocation-free) ----------------
__device__ __half g_xh[Nn * FIN];      // x hi limb fp16, 8MB
__device__ __half g_xl[Nn * FIN];      // x lo limb
__device__ __half g_wh[FOUT * FIN];    // W^T hi limb [n][k]
__device__ __half g_wl[FOUT * FIN];    // W^T lo limb
__device__ __half g_hT[FOUT * Nn];     // h transposed fp16 [feat][node], 2MB
__device__ float  g_part[2 * NF];      // K-split partial sums, 8MB
__device__ float  g_degp[2 * Nn];      // K-split partial degrees
__device__ float  g_qpart[128];        // per-block qmp partials

// ---------------- PTX helpers ----------------
__device__ __forceinline__ uint32_t smem_u32(const void* p) {
    uint32_t a;
    asm("{ .reg .u64 t; cvta.to.shared.u64 t, %1; cvt.u32.u64 %0, t; }" : "=r"(a) : "l"(p));
    return a;
}
#define CP16(dst, src) \
    asm volatile("cp.async.cg.shared.global [%0], [%1], 16;" :: "r"(dst), "l"(src) : "memory")
#define CP_COMMIT() asm volatile("cp.async.commit_group;" ::: "memory")
#define CP_WAIT1()  asm volatile("cp.async.wait_group 1;" ::: "memory")
#define CP_WAIT0()  asm volatile("cp.async.wait_group 0;" ::: "memory")

#define LDSM4(r0, r1, r2, r3, addr) \
    asm volatile("ldmatrix.sync.aligned.m8n8.x4.shared.b16 {%0,%1,%2,%3},[%4];" \
        : "=r"(r0), "=r"(r1), "=r"(r2), "=r"(r3) : "r"(addr))

#define MMAH(acc, a0, a1, a2, a3, b0, b1) \
    asm volatile("mma.sync.aligned.m16n8k16.row.col.f32.f16.f16.f32 " \
        "{%0,%1,%2,%3},{%4,%5,%6,%7},{%8,%9},{%0,%1,%2,%3};" \
        : "+f"((acc)[0]), "+f"((acc)[1]), "+f"((acc)[2]), "+f"((acc)[3]) \
        : "r"(a0), "r"(a1), "r"(a2), "r"(a3), "r"(b0), "r"(b1))

#define STS128(addr, v) \
    asm volatile("st.shared.v4.b32 [%0], {%1, %2, %3, %4};" \
                 :: "r"(addr), "r"((v).x), "r"((v).y), "r"((v).z), "r"((v).w) : "memory")

__device__ __forceinline__ uint32_t pkh(int x, int y) {   // 2x int{0,1} -> fp16x2
    return (x ? 0x3C00u : 0u) | (y ? 0x3C000000u : 0u);
}
__device__ __forceinline__ uint32_t pk2f(float a, float b) {
    __half ha = __float2half_rn(a), hb = __float2half_rn(b);
    return (uint32_t)__half_as_ushort(ha) | ((uint32_t)__half_as_ushort(hb) << 16);
}

// ---------------- kernel 0a: x -> 2-limb fp16 ----------------
__global__ void __launch_bounds__(256) k0_convx(const float* __restrict__ x)
{
    const int i = (blockIdx.x * 256 + threadIdx.x) * 4;
    float4 v = *(const float4*)&x[i];
    __half hx = __float2half_rn(v.x), hy = __float2half_rn(v.y);
    __half hz = __float2half_rn(v.z), hw = __float2half_rn(v.w);
    uint2 hp, lp;
    hp.x = (uint32_t)__half_as_ushort(hx) | ((uint32_t)__half_as_ushort(hy) << 16);
    hp.y = (uint32_t)__half_as_ushort(hz) | ((uint32_t)__half_as_ushort(hw) << 16);
    lp.x = pk2f(v.x - __half2float(hx), v.y - __half2float(hy));
    lp.y = pk2f(v.z - __half2float(hz), v.w - __half2float(hw));
    *(uint2*)&g_xh[i] = hp;
    *(uint2*)&g_xl[i] = lp;
}

// ---------------- kernel 0b: W -> transposed 2-limb fp16 ----------------
__global__ void __launch_bounds__(256) k0_convw(const float* __restrict__ W)
{
    const int idx = blockIdx.x * 256 + threadIdx.x;   // 0..65535
    const int n = idx >> 9, k = idx & 511;
    float v = W[k * FOUT + n];
    __half h = __float2half_rn(v);
    g_wh[idx] = h;
    g_wl[idx] = __float2half_rn(v - __half2float(h));
}

// ---------------- kernel 1: h = x@W via 2-limb fp16 HMMA; hT emit + qmp ----
#define XHO 0
#define XLO 33792
#define WHO 67584
#define WLO 135168
#define K1STR 528
#define K1_SMEM 202752

__global__ void __launch_bounds__(256) k1_gemm(
    const float* __restrict__ w1, const float* __restrict__ b1,
    const float* __restrict__ w21, const float* __restrict__ b21,
    const float* __restrict__ w22, const float* __restrict__ b22)
{
    extern __shared__ __align__(128) char sm1[];
    const uint32_t sb = smem_u32(sm1);
    const int t = threadIdx.x;
    const int w = t >> 5, l = t & 31;
    const int wm = w & 1, wn = w >> 1;     // 2x4 warps; warp tile 32 rows x 32 cols
    const int m0 = blockIdx.x * 64;

    float acc[2][4][4];
    #pragma unroll
    for (int m = 0; m < 2; m++)
        #pragma unroll
        for (int j = 0; j < 4; j++)
            #pragma unroll
            for (int q = 0; q < 4; q++) acc[m][j][q] = 0.0f;

    const uint32_t aH = sb + XHO + (wm * 32 + (l & 15)) * K1STR + ((l >> 4) * 8) * 2;
    const uint32_t aL = aH + (XLO - XHO);
    const int bn_lane = (l & 7) | ((l >> 4) << 3);
    const int bc_lane = ((l >> 3) & 1) << 3;
    const uint32_t bH = sb + WHO + (wn * 32 + bn_lane) * K1STR + bc_lane * 2;
    const uint32_t bL = bH + (WLO - WHO);

    for (int ch = 0; ch < 2; ch++) {
        for (int i = t; i < 2048; i += 256) {
            int row = i >> 5, seg = i & 31;
            size_t so = ((size_t)(m0 + row) * FIN + ch * 256) * 2 + seg * 16;
            CP16(sb + XHO + row * K1STR + seg * 16, (const char*)g_xh + so);
            CP16(sb + XLO + row * K1STR + seg * 16, (const char*)g_xl + so);
        }
        for (int i = t; i < 4096; i += 256) {
            int row = i >> 5, seg = i & 31;
            size_t so = ((size_t)row * FIN + ch * 256) * 2 + seg * 16;
            CP16(sb + WHO + row * K1STR + seg * 16, (const char*)g_wh + so);
            CP16(sb + WLO + row * K1STR + seg * 16, (const char*)g_wl + so);
        }
        CP_COMMIT();
        CP_WAIT0();
        __syncthreads();

        #pragma unroll 4
        for (int kk = 0; kk < 256; kk += 16) {
            uint32_t ah[2][4], al[2][4];
            LDSM4(ah[0][0], ah[0][1], ah[0][2], ah[0][3], aH + kk * 2);
            LDSM4(ah[1][0], ah[1][1], ah[1][2], ah[1][3], aH + 16 * K1STR + kk * 2);
            LDSM4(al[0][0], al[0][1], al[0][2], al[0][3], aL + kk * 2);
            LDSM4(al[1][0], al[1][1], al[1][2], al[1][3], aL + 16 * K1STR + kk * 2);
            #pragma unroll
            for (int n16 = 0; n16 < 2; n16++) {
                uint32_t bh0, bh1, bh2, bh3, bl0, bl1, bl2, bl3;
                LDSM4(bh0, bh1, bh2, bh3, bH + n16 * 16 * K1STR + kk * 2);
                LDSM4(bl0, bl1, bl2, bl3, bL + n16 * 16 * K1STR + kk * 2);
                #pragma unroll
                for (int m = 0; m < 2; m++) {
                    MMAH(acc[m][2 * n16],     ah[m][0], ah[m][1], ah[m][2], ah[m][3], bh0, bh1);
                    MMAH(acc[m][2 * n16 + 1], ah[m][0], ah[m][1], ah[m][2], ah[m][3], bh2, bh3);
                    MMAH(acc[m][2 * n16],     al[m][0], al[m][1], al[m][2], al[m][3], bh0, bh1);
                    MMAH(acc[m][2 * n16 + 1], al[m][0], al[m][1], al[m][2], al[m][3], bh2, bh3);
                    MMAH(acc[m][2 * n16],     ah[m][0], ah[m][1], ah[m][2], ah[m][3], bl0, bl1);
                    MMAH(acc[m][2 * n16 + 1], ah[m][0], ah[m][1], ah[m][2], ah[m][3], bl2, bl3);
                }
            }
        }
        __syncthreads();
    }

    // ---- epilogue ----
    float* h_s = (float*)sm1;                 // [64][133]
    float* v1s = (float*)(sm1 + 34048);       // [16][128]
    float* sml = (float*)(sm1 + 42240);
    #pragma unroll
    for (int m = 0; m < 2; m++) {
        const int row = wm * 32 + m * 16 + (l >> 2);
        #pragma unroll
        for (int j = 0; j < 4; j++) {
            const int col = wn * 32 + j * 8 + 2 * (l & 3);
            h_s[row * 133 + col]           = acc[m][j][0];
            h_s[row * 133 + col + 1]       = acc[m][j][1];
            h_s[(row + 8) * 133 + col]     = acc[m][j][2];
            h_s[(row + 8) * 133 + col + 1] = acc[m][j][3];
        }
    }
    for (int i = t; i < HID * FOUT; i += 256) {
        int hh = i >> 7, c = i & 127;
        v1s[i] = w1[hh * 256 + c] + w1[hh * 256 + 128 + c];
    }
    if (t < 16) { sml[t] = b1[t]; sml[16 + t] = w21[t]; sml[32 + t] = w22[t]; }
    if (t == 0) { sml[48] = b21[0]; sml[49] = b22[0]; }
    __syncthreads();

    #pragma unroll
    for (int ii = 0; ii < 4; ii++) {
        int item = t + 256 * ii;
        int n = item >> 3, g = item & 7;
        uint32_t hp[4];
        #pragma unroll
        for (int q2 = 0; q2 < 4; q2++) {
            float v0 = h_s[(g * 8 + 2 * q2) * 133 + n];
            float v1 = h_s[(g * 8 + 2 * q2 + 1) * 133 + n];
            hp[q2] = pk2f(v0, v1);
        }
        size_t off = (size_t)n * Nn + m0 + g * 8;
        *(uint4*)((char*)g_hT + off * 2) = make_uint4(hp[0], hp[1], hp[2], hp[3]);
    }

    float contrib = 0.0f;
    for (int rr = w * 8; rr < w * 8 + 8; rr++) {
        float hv0 = h_s[rr * 133 + l];
        float hv1 = h_s[rr * 133 + l + 32];
        float hv2 = h_s[rr * 133 + l + 64];
        float hv3 = h_s[rr * 133 + l + 96];
        float mu = 0.0f, lv = 0.0f;
        #pragma unroll
        for (int hh = 0; hh < 16; hh++) {
            const float* vr = &v1s[hh * 128];
            float s = hv0 * vr[l] + hv1 * vr[l + 32] + hv2 * vr[l + 64] + hv3 * vr[l + 96];
            #pragma unroll
            for (int o = 16; o > 0; o >>= 1) s += __shfl_xor_sync(0xffffffffu, s, o);
            float u = s + sml[hh];
            u = u > 0.0f ? u : 0.0f;
            mu += u * sml[16 + hh];
            lv += u * sml[32 + hh];
        }
        if (l == 0) {
            mu += sml[48]; lv += sml[49];
            float sig = (lv > 20.0f) ? lv : log1pf(expf(lv));
            contrib += 0.5f * mu * mu - logf(sig);
        }
    }
    __syncthreads();
    if (l == 0) sml[56 + w] = contrib;
    __syncthreads();
    if (t == 0) {
        float s = 0.0f;
        #pragma unroll
        for (int i = 0; i < 8; i++) s += sml[56 + i];
        g_qpart[blockIdx.x] = s;
    }
}

// ---------------- kernel 2: masked aggregation, fp16 HMMA ------------------
// Grid 128 = (mt 0..63) x (ksp 0..1): CTA = 128 rows x K-half 4096, N=128.
// 512 threads, 16 warps in 4x4 grid, warp tile 32x32. Chunk K=128 (32 chunks).
// Buffer: A fp16 [128][272B] (34816B) | B fp16 [128][272B] (34816B); x2 stages.
#define ASTR2  272
#define OFF_B2 34816
#define BUFSZ2 69632
#define NCH    32
#define K2_SMEM (2*BUFSZ2)

__global__ void __launch_bounds__(512, 1) k2_aggr(const int* __restrict__ adj)
{
    extern __shared__ __align__(128) char sm2[];
    const uint32_t sb = smem_u32(sm2);
    const int t = threadIdx.x;
    const int w = t >> 5, l = t & 31;
    const int wm = w & 3, wn = w >> 2;     // 4x4 warps; warp tile 32 rows x 32 cols
    const int mt = blockIdx.x >> 1, ksp = blockIdx.x & 1;
    const int m0 = mt * 128;
    const int kbase = ksp * 4096;

    // ---- loader indexing: A & B both 4 threads/row (128 rows) ----
    const int lr = t >> 2, lq = t & 3;
    const int* aSrc = adj + (size_t)(m0 + lr) * Nn + kbase + lq * 32;
    const uint32_t aDst = sb + lr * ASTR2 + lq * 64;
    const __half* bSrc = g_hT + (size_t)lr * Nn + kbase + lq * 32;
    const uint32_t bDst = sb + OFF_B2 + lr * ASTR2 + lq * 64;

    uint32_t pA[16];    // packed fp16x2 for one staged A quarter-row (32 K values)
    int dacc = 0;

// load + count + pack (each chunk passes through exactly once)
#define LDA(c) do { \
    const int4* _p = (const int4*)(aSrc + (size_t)(c) * 128); \
    _Pragma("unroll") \
    for (int _j = 0; _j < 8; _j++) { \
        int4 _v = _p[_j]; \
        dacc += _v.x + _v.y + _v.z + _v.w; \
        pA[2 * _j]     = pkh(_v.x, _v.y); \
        pA[2 * _j + 1] = pkh(_v.z, _v.w); \
    } } while (0)
#define STA(buf) do { \
    _Pragma("unroll") \
    for (int _j = 0; _j < 4; _j++) \
        STS128(aDst + (buf) * BUFSZ2 + _j * 16, \
               make_uint4(pA[4*_j], pA[4*_j+1], pA[4*_j+2], pA[4*_j+3])); \
    } while (0)
#define CPB(c, buf) do { \
    const char* _s = (const char*)(bSrc + (size_t)(c) * 128); \
    uint32_t _d = bDst + (buf) * BUFSZ2; \
    CP16(_d, _s);          CP16(_d + 16, _s + 16); \
    CP16(_d + 32, _s + 32); CP16(_d + 48, _s + 48); \
    } while (0)

    float acc[2][4][4];
    #pragma unroll
    for (int m = 0; m < 2; m++)
        #pragma unroll
        for (int j = 0; j < 4; j++)
            #pragma unroll
            for (int q = 0; q < 4; q++) acc[m][j][q] = 0.0f;

    // prologue
    LDA(0);
    CPB(0, 0); CP_COMMIT();
    CPB(1, 1); CP_COMMIT();
    STA(0);
    LDA(1);

    // fragment addressing (R8-proven lane maps)
    const uint32_t aLane = sb + (wm * 32 + (l & 15)) * ASTR2 + ((l >> 4) * 8) * 2;
    const int bn_lane = (l & 7) | ((l >> 4) << 3);
    const int bc_lane = ((l >> 3) & 1) << 3;
    const uint32_t bLane0 = sb + OFF_B2 + (wn * 32 + bn_lane) * ASTR2 + bc_lane * 2;
    const uint32_t bLane1 = bLane0 + 16 * ASTR2;

    for (int c = 0; c < NCH; c++) {
        CP_WAIT1();
        __syncthreads();
        const int buf = c & 1;
        if (c + 1 < NCH) STA(buf ^ 1);
        if (c + 2 < NCH) LDA(c + 2);

        const uint32_t aB0 = aLane + buf * BUFSZ2;
        const uint32_t aB1 = aB0 + 16 * ASTR2;
        const uint32_t bB0 = bLane0 + buf * BUFSZ2;
        const uint32_t bB1 = bLane1 + buf * BUFSZ2;
        #pragma unroll
        for (int kk = 0; kk < 128; kk += 16) {
            uint32_t a0[4], a1[4], b0, b1, b2, b3;
            LDSM4(a0[0], a0[1], a0[2], a0[3], aB0 + kk * 2);
            LDSM4(a1[0], a1[1], a1[2], a1[3], aB1 + kk * 2);
            LDSM4(b0, b1, b2, b3, bB0 + kk * 2);
            MMAH(acc[0][0], a0[0], a0[1], a0[2], a0[3], b0, b1);
            MMAH(acc[0][1], a0[0], a0[1], a0[2], a0[3], b2, b3);
            MMAH(acc[1][0], a1[0], a1[1], a1[2], a1[3], b0, b1);
            MMAH(acc[1][1], a1[0], a1[1], a1[2], a1[3], b2, b3);
            LDSM4(b0, b1, b2, b3, bB1 + kk * 2);
            MMAH(acc[0][2], a0[0], a0[1], a0[2], a0[3], b0, b1);
            MMAH(acc[0][3], a0[0], a0[1], a0[2], a0[3], b2, b3);
            MMAH(acc[1][2], a1[0], a1[1], a1[2], a1[3], b0, b1);
            MMAH(acc[1][3], a1[0], a1[1], a1[2], a1[3], b2, b3);
        }
        __syncthreads();
        if (c + 2 < NCH) CPB(c + 2, buf);
        CP_COMMIT();
    }
#undef LDA
#undef STA
#undef CPB

    // ---- degrees: reduce over the 4 loader threads per row ----
    dacc += __shfl_xor_sync(0xffffffffu, dacc, 1);
    dacc += __shfl_xor_sync(0xffffffffu, dacc, 2);
    if (lq == 0) g_degp[ksp * Nn + m0 + lr] = (float)dacc;

    // ---- epilogue: K-split partials ----
    float* slab = g_part + (size_t)ksp * NF;
    #pragma unroll
    for (int m = 0; m < 2; m++) {
        const int row = m0 + wm * 32 + m * 16 + (l >> 2);
        #pragma unroll
        for (int j = 0; j < 4; j++) {
            const int col = wn * 32 + j * 8 + 2 * (l & 3);
            *(float2*)&slab[(size_t)row * FOUT + col] =
                make_float2(acc[m][j][0], acc[m][j][1]);
            *(float2*)&slab[(size_t)(row + 8) * FOUT + col] =
                make_float2(acc[m][j][2], acc[m][j][3]);
        }
    }
}

// ---------------- kernel 3: combine K-halves, scale, elu, qmp --------------
__global__ void __launch_bounds__(256) k3_final(float* __restrict__ out, int out_size)
{
    const int idx = blockIdx.x * 256 + threadIdx.x;
    if (idx < NF) {
        const int row = idx >> 7;
        float p = g_part[idx] + g_part[NF + idx];
        float d = g_degp[row] + g_degp[Nn + row];
        float v = d > 0.0f ? p / d : 0.0f;
        out[idx] = v > 0.0f ? v : expm1f(v);
    }
    if (blockIdx.x == 0 && threadIdx.x < 32) {
        float q = g_qpart[threadIdx.x] + g_qpart[threadIdx.x + 32] +
                  g_qpart[threadIdx.x + 64] + g_qpart[threadIdx.x + 96];
        #pragma unroll
        for (int o = 16; o > 0; o >>= 1) q += __shfl_xor_sync(0xffffffffu, q, o);
        if (threadIdx.x == 0 && out_size > NF) out[NF] = q;
    }
}

// ---------------- launch ----------------
extern "C" void kernel_launch(void* const* d_in, const int* in_sizes, int n_in,
                              void* d_out, int out_size) {
    const float* x   = (const float*)d_in[0];
    const int*   adj = (const int*)  d_in[1];
    const float* W   = (const float*)d_in[2];
    const float* w1  = (const float*)d_in[3];
    const float* b1  = (const float*)d_in[4];
    const float* w21 = (const float*)d_in[5];
    const float* b21 = (const float*)d_in[6];
    const float* w22 = (const float*)d_in[7];
    const float* b22 = (const float*)d_in[8];
    float* out = (float*)d_out;

    cudaFuncSetAttribute(k1_gemm, cudaFuncAttributeMaxDynamicSharedMemorySize, K1_SMEM);
    cudaFuncSetAttribute(k2_aggr, cudaFuncAttributeMaxDynamicSharedMemorySize, K2_SMEM);

    k0_convx<<<Nn * FIN / 1024, 256>>>(x);
    k0_convw<<<FOUT * FIN / 256, 256>>>(W);
    k1_gemm<<<Nn / 64, 256, K1_SMEM>>>(w1, b1, w21, b21, w22, b22);
    k2_aggr<<<128, 512, K2_SMEM>>>(adj);
    k3_final<<<(NF + 255) / 256, 256>>>(out, out_size);
}

// round 14
// speedup vs baseline: 1.5984x; 1.5984x over previous
#include <cuda_runtime.h>
#include <cuda_fp16.h>
#include <stdint.h>

#define Nn   8192
#define FIN  512
#define FOUT 128
#define HID  16
#define NF   (Nn*FOUT)

// ---------------- scratch (device globals: allocation-free) ----------------
__device__ __half g_xh[Nn * FIN];      // x hi limb fp16, 8MB
__device__ __half g_xl[Nn * FIN];      // x lo limb
__device__ __half g_wh[FOUT * FIN];    // W^T hi limb [n][k]
__device__ __half g_wl[FOUT * FIN];    // W^T lo limb
__device__ __half g_hT[FOUT * Nn];     // h transposed fp16 [feat][node], 2MB
__device__ float  g_part[2 * NF];      // K-split partial sums, 8MB
__device__ float  g_degp[2 * Nn];      // K-split partial degrees
__device__ float  g_qpart[128];        // per-block qmp partials

// ---------------- PTX helpers ----------------
__device__ __forceinline__ uint32_t smem_u32(const void* p) {
    uint32_t a;
    asm("{ .reg .u64 t; cvta.to.shared.u64 t, %1; cvt.u32.u64 %0, t; }" : "=r"(a) : "l"(p));
    return a;
}
#define CP16(dst, src) \
    asm volatile("cp.async.cg.shared.global [%0], [%1], 16;" :: "r"(dst), "l"(src) : "memory")
#define CP_COMMIT() asm volatile("cp.async.commit_group;" ::: "memory")
#define CP_WAIT1()  asm volatile("cp.async.wait_group 1;" ::: "memory")
#define CP_WAIT0()  asm volatile("cp.async.wait_group 0;" ::: "memory")

#define LDSM4(r0, r1, r2, r3, addr) \
    asm volatile("ldmatrix.sync.aligned.m8n8.x4.shared.b16 {%0,%1,%2,%3},[%4];" \
        : "=r"(r0), "=r"(r1), "=r"(r2), "=r"(r3) : "r"(addr))

#define MMAH(acc, a0, a1, a2, a3, b0, b1) \
    asm volatile("mma.sync.aligned.m16n8k16.row.col.f32.f16.f16.f32 " \
        "{%0,%1,%2,%3},{%4,%5,%6,%7},{%8,%9},{%0,%1,%2,%3};" \
        : "+f"((acc)[0]), "+f"((acc)[1]), "+f"((acc)[2]), "+f"((acc)[3]) \
        : "r"(a0), "r"(a1), "r"(a2), "r"(a3), "r"(b0), "r"(b1))

#define STS128(addr, v) \
    asm volatile("st.shared.v4.b32 [%0], {%1, %2, %3, %4};" \
                 :: "r"(addr), "r"((v).x), "r"((v).y), "r"((v).z), "r"((v).w) : "memory")

__device__ __forceinline__ uint32_t pkh(int x, int y) {   // 2x int{0,1} -> fp16x2
    return (x ? 0x3C00u : 0u) | (y ? 0x3C000000u : 0u);
}
__device__ __forceinline__ uint32_t pk2f(float a, float b) {
    __half ha = __float2half_rn(a), hb = __float2half_rn(b);
    return (uint32_t)__half_as_ushort(ha) | ((uint32_t)__half_as_ushort(hb) << 16);
}

// ---------------- kernel 0a: x -> 2-limb fp16 ----------------
__global__ void __launch_bounds__(256) k0_convx(const float* __restrict__ x)
{
    const int i = (blockIdx.x * 256 + threadIdx.x) * 4;
    float4 v = *(const float4*)&x[i];
    __half hx = __float2half_rn(v.x), hy = __float2half_rn(v.y);
    __half hz = __float2half_rn(v.z), hw = __float2half_rn(v.w);
    uint2 hp, lp;
    hp.x = (uint32_t)__half_as_ushort(hx) | ((uint32_t)__half_as_ushort(hy) << 16);
    hp.y = (uint32_t)__half_as_ushort(hz) | ((uint32_t)__half_as_ushort(hw) << 16);
    lp.x = pk2f(v.x - __half2float(hx), v.y - __half2float(hy));
    lp.y = pk2f(v.z - __half2float(hz), v.w - __half2float(hw));
    *(uint2*)&g_xh[i] = hp;
    *(uint2*)&g_xl[i] = lp;
}

// ---------------- kernel 0b: W -> transposed 2-limb fp16 ----------------
__global__ void __launch_bounds__(256) k0_convw(const float* __restrict__ W)
{
    const int idx = blockIdx.x * 256 + threadIdx.x;   // 0..65535
    const int n = idx >> 9, k = idx & 511;
    float v = W[k * FOUT + n];
    __half h = __float2half_rn(v);
    g_wh[idx] = h;
    g_wl[idx] = __float2half_rn(v - __half2float(h));
}

// ---------------- kernel 1: h = x@W via 2-limb fp16 HMMA; hT emit + qmp ----
#define XHO 0
#define XLO 33792
#define WHO 67584
#define WLO 135168
#define K1STR 528
#define K1_SMEM 202752

__global__ void __launch_bounds__(256) k1_gemm(
    const float* __restrict__ w1, const float* __restrict__ b1,
    const float* __restrict__ w21, const float* __restrict__ b21,
    const float* __restrict__ w22, const float* __restrict__ b22)
{
    extern __shared__ __align__(128) char sm1[];
    const uint32_t sb = smem_u32(sm1);
    const int t = threadIdx.x;
    const int w = t >> 5, l = t & 31;
    const int wm = w & 1, wn = w >> 1;     // 2x4 warps; warp tile 32 rows x 32 cols
    const int m0 = blockIdx.x * 64;

    float acc[2][4][4];
    #pragma unroll
    for (int m = 0; m < 2; m++)
        #pragma unroll
        for (int j = 0; j < 4; j++)
            #pragma unroll
            for (int q = 0; q < 4; q++) acc[m][j][q] = 0.0f;

    const uint32_t aH = sb + XHO + (wm * 32 + (l & 15)) * K1STR + ((l >> 4) * 8) * 2;
    const uint32_t aL = aH + (XLO - XHO);
    const int bn_lane = (l & 7) | ((l >> 4) << 3);
    const int bc_lane = ((l >> 3) & 1) << 3;
    const uint32_t bH = sb + WHO + (wn * 32 + bn_lane) * K1STR + bc_lane * 2;
    const uint32_t bL = bH + (WLO - WHO);

    for (int ch = 0; ch < 2; ch++) {
        for (int i = t; i < 2048; i += 256) {
            int row = i >> 5, seg = i & 31;
            size_t so = ((size_t)(m0 + row) * FIN + ch * 256) * 2 + seg * 16;
            CP16(sb + XHO + row * K1STR + seg * 16, (const char*)g_xh + so);
            CP16(sb + XLO + row * K1STR + seg * 16, (const char*)g_xl + so);
        }
        for (int i = t; i < 4096; i += 256) {
            int row = i >> 5, seg = i & 31;
            size_t so = ((size_t)row * FIN + ch * 256) * 2 + seg * 16;
            CP16(sb + WHO + row * K1STR + seg * 16, (const char*)g_wh + so);
            CP16(sb + WLO + row * K1STR + seg * 16, (const char*)g_wl + so);
        }
        CP_COMMIT();
        CP_WAIT0();
        __syncthreads();

        #pragma unroll 4
        for (int kk = 0; kk < 256; kk += 16) {
            uint32_t ah[2][4], al[2][4];
            LDSM4(ah[0][0], ah[0][1], ah[0][2], ah[0][3], aH + kk * 2);
            LDSM4(ah[1][0], ah[1][1], ah[1][2], ah[1][3], aH + 16 * K1STR + kk * 2);
            LDSM4(al[0][0], al[0][1], al[0][2], al[0][3], aL + kk * 2);
            LDSM4(al[1][0], al[1][1], al[1][2], al[1][3], aL + 16 * K1STR + kk * 2);
            #pragma unroll
            for (int n16 = 0; n16 < 2; n16++) {
                uint32_t bh0, bh1, bh2, bh3, bl0, bl1, bl2, bl3;
                LDSM4(bh0, bh1, bh2, bh3, bH + n16 * 16 * K1STR + kk * 2);
                LDSM4(bl0, bl1, bl2, bl3, bL + n16 * 16 * K1STR + kk * 2);
                #pragma unroll
                for (int m = 0; m < 2; m++) {
                    MMAH(acc[m][2 * n16],     ah[m][0], ah[m][1], ah[m][2], ah[m][3], bh0, bh1);
                    MMAH(acc[m][2 * n16 + 1], ah[m][0], ah[m][1], ah[m][2], ah[m][3], bh2, bh3);
                    MMAH(acc[m][2 * n16],     al[m][0], al[m][1], al[m][2], al[m][3], bh0, bh1);
                    MMAH(acc[m][2 * n16 + 1], al[m][0], al[m][1], al[m][2], al[m][3], bh2, bh3);
                    MMAH(acc[m][2 * n16],     ah[m][0], ah[m][1], ah[m][2], ah[m][3], bl0, bl1);
                    MMAH(acc[m][2 * n16 + 1], ah[m][0], ah[m][1], ah[m][2], ah[m][3], bl2, bl3);
                }
            }
        }
        __syncthreads();
    }

    // ---- epilogue ----
    float* h_s = (float*)sm1;                 // [64][133]
    float* v1s = (float*)(sm1 + 34048);       // [16][128]
    float* sml = (float*)(sm1 + 42240);
    #pragma unroll
    for (int m = 0; m < 2; m++) {
        const int row = wm * 32 + m * 16 + (l >> 2);
        #pragma unroll
        for (int j = 0; j < 4; j++) {
            const int col = wn * 32 + j * 8 + 2 * (l & 3);
            h_s[row * 133 + col]           = acc[m][j][0];
            h_s[row * 133 + col + 1]       = acc[m][j][1];
            h_s[(row + 8) * 133 + col]     = acc[m][j][2];
            h_s[(row + 8) * 133 + col + 1] = acc[m][j][3];
        }
    }
    for (int i = t; i < HID * FOUT; i += 256) {
        int hh = i >> 7, c = i & 127;
        v1s[i] = w1[hh * 256 + c] + w1[hh * 256 + 128 + c];
    }
    if (t < 16) { sml[t] = b1[t]; sml[16 + t] = w21[t]; sml[32 + t] = w22[t]; }
    if (t == 0) { sml[48] = b21[0]; sml[49] = b22[0]; }
    __syncthreads();

    #pragma unroll
    for (int ii = 0; ii < 4; ii++) {
        int item = t + 256 * ii;
        int n = item >> 3, g = item & 7;
        uint32_t hp[4];
        #pragma unroll
        for (int q2 = 0; q2 < 4; q2++) {
            float v0 = h_s[(g * 8 + 2 * q2) * 133 + n];
            float v1 = h_s[(g * 8 + 2 * q2 + 1) * 133 + n];
            hp[q2] = pk2f(v0, v1);
        }
        size_t off = (size_t)n * Nn + m0 + g * 8;
        *(uint4*)((char*)g_hT + off * 2) = make_uint4(hp[0], hp[1], hp[2], hp[3]);
    }

    float contrib = 0.0f;
    for (int rr = w * 8; rr < w * 8 + 8; rr++) {
        float hv0 = h_s[rr * 133 + l];
        float hv1 = h_s[rr * 133 + l + 32];
        float hv2 = h_s[rr * 133 + l + 64];
        float hv3 = h_s[rr * 133 + l + 96];
        float mu = 0.0f, lv = 0.0f;
        #pragma unroll
        for (int hh = 0; hh < 16; hh++) {
            const float* vr = &v1s[hh * 128];
            float s = hv0 * vr[l] + hv1 * vr[l + 32] + hv2 * vr[l + 64] + hv3 * vr[l + 96];
            #pragma unroll
            for (int o = 16; o > 0; o >>= 1) s += __shfl_xor_sync(0xffffffffu, s, o);
            float u = s + sml[hh];
            u = u > 0.0f ? u : 0.0f;
            mu += u * sml[16 + hh];
            lv += u * sml[32 + hh];
        }
        if (l == 0) {
            mu += sml[48]; lv += sml[49];
            float sig = (lv > 20.0f) ? lv : log1pf(expf(lv));
            contrib += 0.5f * mu * mu - logf(sig);
        }
    }
    __syncthreads();
    if (l == 0) sml[56 + w] = contrib;
    __syncthreads();
    if (t == 0) {
        float s = 0.0f;
        #pragma unroll
        for (int i = 0; i < 8; i++) s += sml[56 + i];
        g_qpart[blockIdx.x] = s;
    }
}

// ---------------- kernel 2: masked aggregation, fp16 HMMA ------------------
// Grid 128 = (mt 0..63) x (ksp 0..1): CTA = 128 rows x K-half 4096, N=128.
// 512 threads, 16 warps in 4x4 grid, warp tile 32x32, chunk K=64 (R8-proven).
// THREE buffers (A 18432B + B 18432B each) -> ONE __syncthreads per chunk.
#define ASTR2  144
#define OFF_B2 18432
#define BUFSZ2 36864
#define NCH    64
#define K2_SMEM (3*BUFSZ2)

__global__ void __launch_bounds__(512, 1) k2_aggr(const int* __restrict__ adj)
{
    extern __shared__ __align__(128) char sm2[];
    const uint32_t sb = smem_u32(sm2);
    const int t = threadIdx.x;
    const int w = t >> 5, l = t & 31;
    const int wm = w & 3, wn = w >> 2;     // 4x4 warps; warp tile 32 rows x 32 cols
    const int mt = blockIdx.x >> 1, ksp = blockIdx.x & 1;
    const int m0 = mt * 128;
    const int kbase = ksp * 4096;

    // ---- loader indexing: A & B both 4 threads/row (128 rows) ----
    const int lr = t >> 2, lq = t & 3;
    const int* aSrc = adj + (size_t)(m0 + lr) * Nn + kbase + lq * 16;
    const uint32_t aDst = sb + lr * ASTR2 + lq * 32;
    const __half* bSrc = g_hT + (size_t)lr * Nn + kbase + lq * 16;
    const uint32_t bDst = sb + OFF_B2 + lr * ASTR2 + lq * 32;

    int4 rA[4];
    int dacc = 0;

#define LDA(c) do { \
    const int4* _p = (const int4*)(aSrc + (size_t)(c) * 64); \
    rA[0] = _p[0]; rA[1] = _p[1]; rA[2] = _p[2]; rA[3] = _p[3]; } while (0)
#define STA(buf) do { \
    dacc += rA[0].x + rA[0].y + rA[0].z + rA[0].w + rA[1].x + rA[1].y + rA[1].z + rA[1].w \
          + rA[2].x + rA[2].y + rA[2].z + rA[2].w + rA[3].x + rA[3].y + rA[3].z + rA[3].w; \
    uint4 p0, p1; \
    p0.x = pkh(rA[0].x, rA[0].y); p0.y = pkh(rA[0].z, rA[0].w); \
    p0.z = pkh(rA[1].x, rA[1].y); p0.w = pkh(rA[1].z, rA[1].w); \
    p1.x = pkh(rA[2].x, rA[2].y); p1.y = pkh(rA[2].z, rA[2].w); \
    p1.z = pkh(rA[3].x, rA[3].y); p1.w = pkh(rA[3].z, rA[3].w); \
    STS128(aDst + (buf) * BUFSZ2, p0); \
    STS128(aDst + (buf) * BUFSZ2 + 16, p1); } while (0)
#define CPB(c, buf) do { \
    const char* _s = (const char*)(bSrc + (size_t)(c) * 64); \
    uint32_t _d = bDst + (buf) * BUFSZ2; \
    CP16(_d, _s); CP16(_d + 16, _s + 16); } while (0)

    float acc[2][4][4];
    #pragma unroll
    for (int m = 0; m < 2; m++)
        #pragma unroll
        for (int j = 0; j < 4; j++)
            #pragma unroll
            for (int q = 0; q < 4; q++) acc[m][j][q] = 0.0f;

    // ---- prologue: A(0)->buf0, A(1)->buf1 staged; A(2) in regs.
    //      B(0)->buf0 (commit#0), B(1)->buf1 (commit#1).
    LDA(0); STA(0);
    LDA(1); STA(1);
    LDA(2);
    CPB(0, 0); CP_COMMIT();
    CPB(1, 1); CP_COMMIT();

    // fragment addressing (R8-proven lane maps)
    const uint32_t aLane = sb + (wm * 32 + (l & 15)) * ASTR2 + ((l >> 4) * 8) * 2;
    const int bn_lane = (l & 7) | ((l >> 4) << 3);
    const int bc_lane = ((l >> 3) & 1) << 3;
    const uint32_t bLane0 = sb + OFF_B2 + (wn * 32 + bn_lane) * ASTR2 + bc_lane * 2;
    const uint32_t bLane1 = bLane0 + 16 * ASTR2;

    int buf = 0;                     // buf = c % 3
    for (int c = 0; c < NCH; c++) {
        CP_WAIT1();                  // B(c) landed (B(c+1) may be in flight)
        __syncthreads();             // everyone done with chunk c-1; A(c)/B(c) visible

        // refill buffer (c+2)%3 == (c-1)%3 — drained at iteration c-1
        const int nbuf = (buf + 2 >= 3) ? buf - 1 : buf + 2;
        if (c + 2 < NCH) { CPB(c + 2, nbuf); }
        CP_COMMIT();                 // commit even if empty (keeps group ledger aligned)
        if (c + 2 < NCH) { STA(nbuf); }
        if (c + 3 < NCH) { LDA(c + 3); }

        const uint32_t aB0 = aLane + buf * BUFSZ2;
        const uint32_t aB1 = aB0 + 16 * ASTR2;
        const uint32_t bB0 = bLane0 + buf * BUFSZ2;
        const uint32_t bB1 = bLane1 + buf * BUFSZ2;
        #pragma unroll
        for (int kk = 0; kk < 64; kk += 16) {
            uint32_t a0[4], a1[4], b0, b1, b2, b3;
            LDSM4(a0[0], a0[1], a0[2], a0[3], aB0 + kk * 2);
            LDSM4(a1[0], a1[1], a1[2], a1[3], aB1 + kk * 2);
            LDSM4(b0, b1, b2, b3, bB0 + kk * 2);
            MMAH(acc[0][0], a0[0], a0[1], a0[2], a0[3], b0, b1);
            MMAH(acc[0][1], a0[0], a0[1], a0[2], a0[3], b2, b3);
            MMAH(acc[1][0], a1[0], a1[1], a1[2], a1[3], b0, b1);
            MMAH(acc[1][1], a1[0], a1[1], a1[2], a1[3], b2, b3);
            LDSM4(b0, b1, b2, b3, bB1 + kk * 2);
            MMAH(acc[0][2], a0[0], a0[1], a0[2], a0[3], b0, b1);
            MMAH(acc[0][3], a0[0], a0[1], a0[2], a0[3], b2, b3);
            MMAH(acc[1][2], a1[0], a1[1], a1[2], a1[3], b0, b1);
            MMAH(acc[1][3], a1[0], a1[1], a1[2], a1[3], b2, b3);
        }
        buf = (buf + 1 >= 3) ? 0 : buf + 1;
    }
#undef LDA
#undef STA
#undef CPB

    // ---- degrees: reduce over the 4 loader threads per row ----
    dacc += __shfl_xor_sync(0xffffffffu, dacc, 1);
    dacc += __shfl_xor_sync(0xffffffffu, dacc, 2);
    if (lq == 0) g_degp[ksp * Nn + m0 + lr] = (float)dacc;

    // ---- epilogue: K-split partials ----
    float* slab = g_part + (size_t)ksp * NF;
    #pragma unroll
    for (int m = 0; m < 2; m++) {
        const int row = m0 + wm * 32 + m * 16 + (l >> 2);
        #pragma unroll
        for (int j = 0; j < 4; j++) {
            const int col = wn * 32 + j * 8 + 2 * (l & 3);
            *(float2*)&slab[(size_t)row * FOUT + col] =
                make_float2(acc[m][j][0], acc[m][j][1]);
            *(float2*)&slab[(size_t)(row + 8) * FOUT + col] =
                make_float2(acc[m][j][2], acc[m][j][3]);
        }
    }
}

// ---------------- kernel 3: combine K-halves, scale, elu, qmp --------------
__global__ void __launch_bounds__(256) k3_final(float* __restrict__ out, int out_size)
{
    const int idx = blockIdx.x * 256 + threadIdx.x;
    if (idx < NF) {
        const int row = idx >> 7;
        float p = g_part[idx] + g_part[NF + idx];
        float d = g_degp[row] + g_degp[Nn + row];
        float v = d > 0.0f ? p / d : 0.0f;
        out[idx] = v > 0.0f ? v : expm1f(v);
    }
    if (blockIdx.x == 0 && threadIdx.x < 32) {
        float q = g_qpart[threadIdx.x] + g_qpart[threadIdx.x + 32] +
                  g_qpart[threadIdx.x + 64] + g_qpart[threadIdx.x + 96];
        #pragma unroll
        for (int o = 16; o > 0; o >>= 1) q += __shfl_xor_sync(0xffffffffu, q, o);
        if (threadIdx.x == 0 && out_size > NF) out[NF] = q;
    }
}

// ---------------- launch ----------------
extern "C" void kernel_launch(void* const* d_in, const int* in_sizes, int n_in,
                              void* d_out, int out_size) {
    const float* x   = (const float*)d_in[0];
    const int*   adj = (const int*)  d_in[1];
    const float* W   = (const float*)d_in[2];
    const float* w1  = (const float*)d_in[3];
    const float* b1  = (const float*)d_in[4];
    const float* w21 = (const float*)d_in[5];
    const float* b21 = (const float*)d_in[6];
    const float* w22 = (const float*)d_in[7];
    const float* b22 = (const float*)d_in[8];
    float* out = (float*)d_out;

    cudaFuncSetAttribute(k1_gemm, cudaFuncAttributeMaxDynamicSharedMemorySize, K1_SMEM);
    cudaFuncSetAttribute(k2_aggr, cudaFuncAttributeMaxDynamicSharedMemorySize, K2_SMEM);

    k0_convx<<<Nn * FIN / 1024, 256>>>(x);
    k0_convw<<<FOUT * FIN / 256, 256>>>(W);
    k1_gemm<<<Nn / 64, 256, K1_SMEM>>>(w1, b1, w21, b21, w22, b22);
    k2_aggr<<<128, 512, K2_SMEM>>>(adj);
    k3_final<<<(NF + 255) / 256, 256>>>(out, out_size);
}

// round 15
// speedup vs baseline: 1.7029x; 1.0654x over previous
#include <cuda_runtime.h>
#include <cuda_fp16.h>
#include <stdint.h>

#define Nn   8192
#define FIN  512
#define FOUT 128
#define HID  16
#define NF   (Nn*FOUT)

// ---------------- scratch (device globals: allocation-free) ----------------
__device__ __half g_xh[Nn * FIN];      // x hi limb fp16, 8MB
__device__ __half g_xl[Nn * FIN];      // x lo limb
__device__ __half g_wh[FOUT * FIN];    // W^T hi limb [n][k]
__device__ __half g_wl[FOUT * FIN];    // W^T lo limb
__device__ __half g_hT[FOUT * Nn];     // h transposed fp16 [feat][node], 2MB
__device__ float  g_part[2 * NF];      // K-split partial sums, 8MB
__device__ float  g_degp[2 * Nn];      // K-split partial degrees
__device__ float  g_qpart[128];        // per-block qmp partials

// ---------------- PTX helpers ----------------
__device__ __forceinline__ uint32_t smem_u32(const void* p) {
    uint32_t a;
    asm("{ .reg .u64 t; cvta.to.shared.u64 t, %1; cvt.u32.u64 %0, t; }" : "=r"(a) : "l"(p));
    return a;
}
#define CP16(dst, src) \
    asm volatile("cp.async.cg.shared.global [%0], [%1], 16;" :: "r"(dst), "l"(src) : "memory")
#define CP_COMMIT() asm volatile("cp.async.commit_group;" ::: "memory")
#define CP_WAIT1()  asm volatile("cp.async.wait_group 1;" ::: "memory")
#define CP_WAIT0()  asm volatile("cp.async.wait_group 0;" ::: "memory")

#define LDSM4(r0, r1, r2, r3, addr) \
    asm volatile("ldmatrix.sync.aligned.m8n8.x4.shared.b16 {%0,%1,%2,%3},[%4];" \
        : "=r"(r0), "=r"(r1), "=r"(r2), "=r"(r3) : "r"(addr))

#define MMAH(acc, a0, a1, a2, a3, b0, b1) \
    asm volatile("mma.sync.aligned.m16n8k16.row.col.f32.f16.f16.f32 " \
        "{%0,%1,%2,%3},{%4,%5,%6,%7},{%8,%9},{%0,%1,%2,%3};" \
        : "+f"((acc)[0]), "+f"((acc)[1]), "+f"((acc)[2]), "+f"((acc)[3]) \
        : "r"(a0), "r"(a1), "r"(a2), "r"(a3), "r"(b0), "r"(b1))

#define STS128(addr, v) \
    asm volatile("st.shared.v4.b32 [%0], {%1, %2, %3, %4};" \
                 :: "r"(addr), "r"((v).x), "r"((v).y), "r"((v).z), "r"((v).w) : "memory")

__device__ __forceinline__ uint32_t pkh(int x, int y) {   // 2x int{0,1} -> fp16x2
    return (x ? 0x3C00u : 0u) | (y ? 0x3C000000u : 0u);
}
__device__ __forceinline__ uint32_t pk2f(float a, float b) {
    __half ha = __float2half_rn(a), hb = __float2half_rn(b);
    return (uint32_t)__half_as_ushort(ha) | ((uint32_t)__half_as_ushort(hb) << 16);
}

// ---------------- kernel 0: x and W -> 2-limb fp16 (merged) ----------------
// blocks [0, 4096): x path; blocks [4096, 4352): W path.
__global__ void __launch_bounds__(256) k0_conv(const float* __restrict__ x,
                                               const float* __restrict__ W)
{
    if (blockIdx.x < 4096) {
        const int i = (blockIdx.x * 256 + threadIdx.x) * 4;
        float4 v = *(const float4*)&x[i];
        __half hx = __float2half_rn(v.x), hy = __float2half_rn(v.y);
        __half hz = __float2half_rn(v.z), hw = __float2half_rn(v.w);
        uint2 hp, lp;
        hp.x = (uint32_t)__half_as_ushort(hx) | ((uint32_t)__half_as_ushort(hy) << 16);
        hp.y = (uint32_t)__half_as_ushort(hz) | ((uint32_t)__half_as_ushort(hw) << 16);
        lp.x = pk2f(v.x - __half2float(hx), v.y - __half2float(hy));
        lp.y = pk2f(v.z - __half2float(hz), v.w - __half2float(hw));
        *(uint2*)&g_xh[i] = hp;
        *(uint2*)&g_xl[i] = lp;
    } else {
        const int idx = (blockIdx.x - 4096) * 256 + threadIdx.x;   // 0..65535
        const int n = idx >> 9, k = idx & 511;
        float v = W[k * FOUT + n];
        __half h = __float2half_rn(v);
        g_wh[idx] = h;
        g_wl[idx] = __float2half_rn(v - __half2float(h));
    }
}

// ---------------- kernel 1: h = x@W via 2-limb fp16 HMMA; hT emit + qmp ----
// 512 threads, 16 warps in 4x4 grid, warp tile 16 rows x 32 cols.
#define XHO 0
#define XLO 33792
#define WHO 67584
#define WLO 135168
#define K1STR 528
#define K1_SMEM 202752

__global__ void __launch_bounds__(512) k1_gemm(
    const float* __restrict__ w1, const float* __restrict__ b1,
    const float* __restrict__ w21, const float* __restrict__ b21,
    const float* __restrict__ w22, const float* __restrict__ b22)
{
    extern __shared__ __align__(128) char sm1[];
    const uint32_t sb = smem_u32(sm1);
    const int t = threadIdx.x;
    const int w = t >> 5, l = t & 31;
    const int wm = w & 3, wn = w >> 2;     // 4x4 warps; warp tile 16 rows x 32 cols
    const int m0 = blockIdx.x * 64;

    float acc[4][4];
    #pragma unroll
    for (int j = 0; j < 4; j++)
        #pragma unroll
        for (int q = 0; q < 4; q++) acc[j][q] = 0.0f;

    const uint32_t aH = sb + XHO + (wm * 16 + (l & 15)) * K1STR + ((l >> 4) * 8) * 2;
    const uint32_t aL = aH + (XLO - XHO);
    const int bn_lane = (l & 7) | ((l >> 4) << 3);
    const int bc_lane = ((l >> 3) & 1) << 3;
    const uint32_t bH = sb + WHO + (wn * 32 + bn_lane) * K1STR + bc_lane * 2;
    const uint32_t bL = bH + (WLO - WHO);

    for (int ch = 0; ch < 2; ch++) {
        for (int i = t; i < 2048; i += 512) {
            int row = i >> 5, seg = i & 31;
            size_t so = ((size_t)(m0 + row) * FIN + ch * 256) * 2 + seg * 16;
            CP16(sb + XHO + row * K1STR + seg * 16, (const char*)g_xh + so);
            CP16(sb + XLO + row * K1STR + seg * 16, (const char*)g_xl + so);
        }
        for (int i = t; i < 4096; i += 512) {
            int row = i >> 5, seg = i & 31;
            size_t so = ((size_t)row * FIN + ch * 256) * 2 + seg * 16;
            CP16(sb + WHO + row * K1STR + seg * 16, (const char*)g_wh + so);
            CP16(sb + WLO + row * K1STR + seg * 16, (const char*)g_wl + so);
        }
        CP_COMMIT();
        CP_WAIT0();
        __syncthreads();

        #pragma unroll 4
        for (int kk = 0; kk < 256; kk += 16) {
            uint32_t ah[4], al[4];
            LDSM4(ah[0], ah[1], ah[2], ah[3], aH + kk * 2);
            LDSM4(al[0], al[1], al[2], al[3], aL + kk * 2);
            #pragma unroll
            for (int n16 = 0; n16 < 2; n16++) {
                uint32_t bh0, bh1, bh2, bh3, bl0, bl1, bl2, bl3;
                LDSM4(bh0, bh1, bh2, bh3, bH + n16 * 16 * K1STR + kk * 2);
                LDSM4(bl0, bl1, bl2, bl3, bL + n16 * 16 * K1STR + kk * 2);
                MMAH(acc[2 * n16],     ah[0], ah[1], ah[2], ah[3], bh0, bh1);
                MMAH(acc[2 * n16 + 1], ah[0], ah[1], ah[2], ah[3], bh2, bh3);
                MMAH(acc[2 * n16],     al[0], al[1], al[2], al[3], bh0, bh1);
                MMAH(acc[2 * n16 + 1], al[0], al[1], al[2], al[3], bh2, bh3);
                MMAH(acc[2 * n16],     ah[0], ah[1], ah[2], ah[3], bl0, bl1);
                MMAH(acc[2 * n16 + 1], ah[0], ah[1], ah[2], ah[3], bl2, bl3);
            }
        }
        __syncthreads();
    }

    // ---- epilogue ----
    float* h_s = (float*)sm1;                 // [64][133]
    float* v1s = (float*)(sm1 + 34048);       // [16][128]
    float* sml = (float*)(sm1 + 42240);       // 192 floats
    {
        const int row = wm * 16 + (l >> 2);
        #pragma unroll
        for (int j = 0; j < 4; j++) {
            const int col = wn * 32 + j * 8 + 2 * (l & 3);
            h_s[row * 133 + col]           = acc[j][0];
            h_s[row * 133 + col + 1]       = acc[j][1];
            h_s[(row + 8) * 133 + col]     = acc[j][2];
            h_s[(row + 8) * 133 + col + 1] = acc[j][3];
        }
    }
    for (int i = t; i < HID * FOUT; i += 512) {
        int hh = i >> 7, c = i & 127;
        v1s[i] = w1[hh * 256 + c] + w1[hh * 256 + 128 + c];
    }
    if (t < 16) { sml[t] = b1[t]; sml[16 + t] = w21[t]; sml[32 + t] = w22[t]; }
    if (t == 0) { sml[48] = b21[0]; sml[49] = b22[0]; }
    __syncthreads();

    // transposed fp16 emit: hT[n][m0+r]
    #pragma unroll
    for (int ii = 0; ii < 2; ii++) {
        int item = t + 512 * ii;               // 0..1023
        int n = item >> 3, g = item & 7;
        uint32_t hp[4];
        #pragma unroll
        for (int q2 = 0; q2 < 4; q2++) {
            float v0 = h_s[(g * 8 + 2 * q2) * 133 + n];
            float v1 = h_s[(g * 8 + 2 * q2 + 1) * 133 + n];
            hp[q2] = pk2f(v0, v1);
        }
        size_t off = (size_t)n * Nn + m0 + g * 8;
        *(uint4*)((char*)g_hT + off * 2) = make_uint4(hp[0], hp[1], hp[2], hp[3]);
    }

    // qmp partials: 16 warps x 4 rows
    float contrib = 0.0f;
    for (int rr = w * 4; rr < w * 4 + 4; rr++) {
        float hv0 = h_s[rr * 133 + l];
        float hv1 = h_s[rr * 133 + l + 32];
        float hv2 = h_s[rr * 133 + l + 64];
        float hv3 = h_s[rr * 133 + l + 96];
        float mu = 0.0f, lv = 0.0f;
        #pragma unroll
        for (int hh = 0; hh < 16; hh++) {
            const float* vr = &v1s[hh * 128];
            float s = hv0 * vr[l] + hv1 * vr[l + 32] + hv2 * vr[l + 64] + hv3 * vr[l + 96];
            #pragma unroll
            for (int o = 16; o > 0; o >>= 1) s += __shfl_xor_sync(0xffffffffu, s, o);
            float u = s + sml[hh];
            u = u > 0.0f ? u : 0.0f;
            mu += u * sml[16 + hh];
            lv += u * sml[32 + hh];
        }
        if (l == 0) {
            mu += sml[48]; lv += sml[49];
            float sig = (lv > 20.0f) ? lv : log1pf(expf(lv));
            contrib += 0.5f * mu * mu - logf(sig);
        }
    }
    __syncthreads();
    if (l == 0) sml[64 + w] = contrib;
    __syncthreads();
    if (t == 0) {
        float s = 0.0f;
        #pragma unroll
        for (int i = 0; i < 16; i++) s += sml[64 + i];
        g_qpart[blockIdx.x] = s;
    }
}

// ---------------- kernel 2: masked aggregation, fp16 HMMA ------------------
// Byte-identical design to R14 (94.0us): 128 CTAs, 512 thr, 4x4 warps of
// 32x32, chunk K=64, 3-stage pipeline, one __syncthreads per chunk.
#define ASTR2  144
#define OFF_B2 18432
#define BUFSZ2 36864
#define NCH    64
#define K2_SMEM (3*BUFSZ2)

__global__ void __launch_bounds__(512, 1) k2_aggr(const int* __restrict__ adj)
{
    extern __shared__ __align__(128) char sm2[];
    const uint32_t sb = smem_u32(sm2);
    const int t = threadIdx.x;
    const int w = t >> 5, l = t & 31;
    const int wm = w & 3, wn = w >> 2;
    const int mt = blockIdx.x >> 1, ksp = blockIdx.x & 1;
    const int m0 = mt * 128;
    const int kbase = ksp * 4096;

    const int lr = t >> 2, lq = t & 3;
    const int* aSrc = adj + (size_t)(m0 + lr) * Nn + kbase + lq * 16;
    const uint32_t aDst = sb + lr * ASTR2 + lq * 32;
    const __half* bSrc = g_hT + (size_t)lr * Nn + kbase + lq * 16;
    const uint32_t bDst = sb + OFF_B2 + lr * ASTR2 + lq * 32;

    int4 rA[4];
    int dacc = 0;

#define LDA(c) do { \
    const int4* _p = (const int4*)(aSrc + (size_t)(c) * 64); \
    rA[0] = _p[0]; rA[1] = _p[1]; rA[2] = _p[2]; rA[3] = _p[3]; } while (0)
#define STA(buf) do { \
    dacc += rA[0].x + rA[0].y + rA[0].z + rA[0].w + rA[1].x + rA[1].y + rA[1].z + rA[1].w \
          + rA[2].x + rA[2].y + rA[2].z + rA[2].w + rA[3].x + rA[3].y + rA[3].z + rA[3].w; \
    uint4 p0, p1; \
    p0.x = pkh(rA[0].x, rA[0].y); p0.y = pkh(rA[0].z, rA[0].w); \
    p0.z = pkh(rA[1].x, rA[1].y); p0.w = pkh(rA[1].z, rA[1].w); \
    p1.x = pkh(rA[2].x, rA[2].y); p1.y = pkh(rA[2].z, rA[2].w); \
    p1.z = pkh(rA[3].x, rA[3].y); p1.w = pkh(rA[3].z, rA[3].w); \
    STS128(aDst + (buf) * BUFSZ2, p0); \
    STS128(aDst + (buf) * BUFSZ2 + 16, p1); } while (0)
#define CPB(c, buf) do { \
    const char* _s = (const char*)(bSrc + (size_t)(c) * 64); \
    uint32_t _d = bDst + (buf) * BUFSZ2; \
    CP16(_d, _s); CP16(_d + 16, _s + 16); } while (0)

    float acc[2][4][4];
    #pragma unroll
    for (int m = 0; m < 2; m++)
        #pragma unroll
        for (int j = 0; j < 4; j++)
            #pragma unroll
            for (int q = 0; q < 4; q++) acc[m][j][q] = 0.0f;

    LDA(0); STA(0);
    LDA(1); STA(1);
    LDA(2);
    CPB(0, 0); CP_COMMIT();
    CPB(1, 1); CP_COMMIT();

    const uint32_t aLane = sb + (wm * 32 + (l & 15)) * ASTR2 + ((l >> 4) * 8) * 2;
    const int bn_lane = (l & 7) | ((l >> 4) << 3);
    const int bc_lane = ((l >> 3) & 1) << 3;
    const uint32_t bLane0 = sb + OFF_B2 + (wn * 32 + bn_lane) * ASTR2 + bc_lane * 2;
    const uint32_t bLane1 = bLane0 + 16 * ASTR2;

    int buf = 0;
    for (int c = 0; c < NCH; c++) {
        CP_WAIT1();
        __syncthreads();

        const int nbuf = (buf + 2 >= 3) ? buf - 1 : buf + 2;
        if (c + 2 < NCH) { CPB(c + 2, nbuf); }
        CP_COMMIT();
        if (c + 2 < NCH) { STA(nbuf); }
        if (c + 3 < NCH) { LDA(c + 3); }

        const uint32_t aB0 = aLane + buf * BUFSZ2;
        const uint32_t aB1 = aB0 + 16 * ASTR2;
        const uint32_t bB0 = bLane0 + buf * BUFSZ2;
        const uint32_t bB1 = bLane1 + buf * BUFSZ2;
        #pragma unroll
        for (int kk = 0; kk < 64; kk += 16) {
            uint32_t a0[4], a1[4], b0, b1, b2, b3;
            LDSM4(a0[0], a0[1], a0[2], a0[3], aB0 + kk * 2);
            LDSM4(a1[0], a1[1], a1[2], a1[3], aB1 + kk * 2);
            LDSM4(b0, b1, b2, b3, bB0 + kk * 2);
            MMAH(acc[0][0], a0[0], a0[1], a0[2], a0[3], b0, b1);
            MMAH(acc[0][1], a0[0], a0[1], a0[2], a0[3], b2, b3);
            MMAH(acc[1][0], a1[0], a1[1], a1[2], a1[3], b0, b1);
            MMAH(acc[1][1], a1[0], a1[1], a1[2], a1[3], b2, b3);
            LDSM4(b0, b1, b2, b3, bB1 + kk * 2);
            MMAH(acc[0][2], a0[0], a0[1], a0[2], a0[3], b0, b1);
            MMAH(acc[0][3], a0[0], a0[1], a0[2], a0[3], b2, b3);
            MMAH(acc[1][2], a1[0], a1[1], a1[2], a1[3], b0, b1);
            MMAH(acc[1][3], a1[0], a1[1], a1[2], a1[3], b2, b3);
        }
        buf = (buf + 1 >= 3) ? 0 : buf + 1;
    }
#undef LDA
#undef STA
#undef CPB

    dacc += __shfl_xor_sync(0xffffffffu, dacc, 1);
    dacc += __shfl_xor_sync(0xffffffffu, dacc, 2);
    if (lq == 0) g_degp[ksp * Nn + m0 + lr] = (float)dacc;

    float* slab = g_part + (size_t)ksp * NF;
    #pragma unroll
    for (int m = 0; m < 2; m++) {
        const int row = m0 + wm * 32 + m * 16 + (l >> 2);
        #pragma unroll
        for (int j = 0; j < 4; j++) {
            const int col = wn * 32 + j * 8 + 2 * (l & 3);
            *(float2*)&slab[(size_t)row * FOUT + col] =
                make_float2(acc[m][j][0], acc[m][j][1]);
            *(float2*)&slab[(size_t)(row + 8) * FOUT + col] =
                make_float2(acc[m][j][2], acc[m][j][3]);
        }
    }
}

// ---------------- kernel 3: combine K-halves, scale, elu, qmp (float4) -----
__global__ void __launch_bounds__(256) k3_final(float* __restrict__ out, int out_size)
{
    const int i4 = (blockIdx.x * 256 + threadIdx.x) * 4;
    if (i4 < NF) {
        const int row = i4 >> 7;
        float4 p0 = *(const float4*)&g_part[i4];
        float4 p1 = *(const float4*)&g_part[NF + i4];
        float d = g_degp[row] + g_degp[Nn + row];
        float inv = d > 0.0f ? 1.0f / d : 0.0f;
        float v0 = (p0.x + p1.x) * inv;
        float v1 = (p0.y + p1.y) * inv;
        float v2 = (p0.z + p1.z) * inv;
        float v3 = (p0.w + p1.w) * inv;
        float4 o;
        o.x = v0 > 0.0f ? v0 : expm1f(v0);
        o.y = v1 > 0.0f ? v1 : expm1f(v1);
        o.z = v2 > 0.0f ? v2 : expm1f(v2);
        o.w = v3 > 0.0f ? v3 : expm1f(v3);
        *(float4*)&out[i4] = o;
    }
    if (blockIdx.x == 0 && threadIdx.x < 32) {
        float q = g_qpart[threadIdx.x] + g_qpart[threadIdx.x + 32] +
                  g_qpart[threadIdx.x + 64] + g_qpart[threadIdx.x + 96];
        #pragma unroll
        for (int o = 16; o > 0; o >>= 1) q += __shfl_xor_sync(0xffffffffu, q, o);
        if (threadIdx.x == 0 && out_size > NF) out[NF] = q;
    }
}

// ---------------- launch ----------------
extern "C" void kernel_launch(void* const* d_in, const int* in_sizes, int n_in,
                              void* d_out, int out_size) {
    const float* x   = (const float*)d_in[0];
    const int*   adj = (const int*)  d_in[1];
    const float* W   = (const float*)d_in[2];
    const float* w1  = (const float*)d_in[3];
    const float* b1  = (const float*)d_in[4];
    const float* w21 = (const float*)d_in[5];
    const float* b21 = (const float*)d_in[6];
    const float* w22 = (const float*)d_in[7];
    const float* b22 = (const float*)d_in[8];
    float* out = (float*)d_out;

    cudaFuncSetAttribute(k1_gemm, cudaFuncAttributeMaxDynamicSharedMemorySize, K1_SMEM);
    cudaFuncSetAttribute(k2_aggr, cudaFuncAttributeMaxDynamicSharedMemorySize, K2_SMEM);

    k0_conv<<<4096 + 256, 256>>>(x, W);
    k1_gemm<<<Nn / 64, 512, K1_SMEM>>>(w1, b1, w21, b21, w22, b22);
    k2_aggr<<<128, 512, K2_SMEM>>>(adj);
    k3_final<<<NF / 1024, 256>>>(out, out_size);
}